// round 13
// baseline (speedup 1.0000x reference)
#include <cuda_runtime.h>
#include <math.h>
#include <stdint.h>

// Shapes: B=4, N=256, F=64, H=256, A=16, T=3
#define Bn 4
#define Nn 256
#define Fn 64
#define Hn 256
#define An 16
#define Tn 3
#define BN 1024
#define NC 1280
#define G 296                 // persistent grid: 2 CTAs/SM x 148 SMs

typedef unsigned long long u64;

// ---------------- scratch (device globals) -----------------------------------
__device__ float d_XT  [Fn*BN];         // X^T
__device__ float d_tT  [Hn*BN];         // pre-hidden^T
__device__ float d_hT  [Hn*BN];         // h^T
__device__ float d_aT  [Hn*BN];         // agg0^T
__device__ float d_M2T [Hn*Hn];         // msg_W2^T
__device__ float d_big2[2*BN*512];      // [hi|hj] row-major, 2 K-split partials
__device__ float d_ghT [2*768*BN];      // gh^T, 2 partials
__device__ float d_giT [4*768*BN];      // gi^T, 4 partials
__device__ float d_deg [BN];
__device__ float d_Wc  [Hn*768];        // msg_W2 @ gru_Wih (row-major)
__device__ float d_bc  [768];           // msg_b2 @ gru_Wih
__device__ float d_Wcat[Hn*NC];         // [W1_i | W1_j | Whh] row-major
__device__ float d_bcat[NC];
__device__ unsigned g_cnt;
__device__ volatile unsigned g_gen;

// ---------------- helpers ------------------------------------------------------
#define FMA2(acc, a, b) \
    asm("fma.rn.f32x2 %0, %1, %2, %0;" : "+l"(acc) : "l"(a), "l"(b))
#define PACKDUP(d, s) \
    asm("mov.b64 %0, {%1, %1};" : "=l"(d) : "f"(s))
#define UNPACK2(lo, hi, s) \
    asm("mov.b64 {%0, %1}, %2;" : "=f"(lo), "=f"(hi) : "l"(s))

__device__ __forceinline__ void cpacg(uint32_t s, const void* g) {
    asm volatile("cp.async.cg.shared.global [%0], [%1], 16;" :: "r"(s), "l"(g));
}

// grid-wide barrier (all G blocks resident by construction)
__device__ __forceinline__ void gridbar() {
    __syncthreads();
    if (threadIdx.x == 0) {
        unsigned gen = g_gen;
        __threadfence();
        if (atomicAdd(&g_cnt, 1u) == G - 1u) {
            g_cnt = 0u;
            __threadfence();
            g_gen = gen + 1u;
        } else {
            while (g_gen == gen) { __nanosleep(32); }
            __threadfence();
        }
    }
    __syncthreads();
}

// ---------------- one 64x128 GEMM tile ----------------------------------------
// 256 thr; warps 2(m)x4(n); thread 4 rows x 8 cols; 3-stage cp.async pipeline.
// C = f(A@B + bias); A TRANSPOSED At[k][m] (ld ldaT), B row-major KxN, K-offset kb.
// col0 < splitCol -> Crow[r][c] (ld ldC); else CtrT[(c-splitCol)][r] (ld ldT).
// smem: As[3][16][68] (13056B) | Bs[3][16][128] (24576B) = 37632B
__device__ __noinline__ void gemm_tile(
    char* smraw,
    const float* At, int ldaT, const float* Bm, int N, int Kt, int kb,
    const float* bias, float* Crow, int ldC, int splitCol,
    float* CtrT, int ldT, int doRelu, int row0, int col0)
{
    float* Asf = (float*)smraw;
    float* Bsf = (float*)(smraw + 13056);
    uint32_t sa  = (uint32_t)__cvta_generic_to_shared(smraw);
    uint32_t sbB = sa + 13056u;

    int tid = threadIdx.x;
    int l = tid & 31, w = tid >> 5;
    int wm = w >> 2, wn = w & 3;
    int rg = l >> 2, cg = l & 3;

    int ak = tid >> 4, am = (tid & 15) << 2;     // A loader: 1x16B
    int bk = tid >> 5, bn = (tid & 31) << 2;     // B loader: 2x16B (bk, bk+8)
    const float* Ab = At + (size_t)kb * ldaT + row0 + am;
    const float* Bb = Bm + (size_t)kb * N + col0 + bn;

    __syncthreads();   // previous tile's smem reads complete

    u64 acc[4][4];
    #pragma unroll
    for (int i = 0; i < 4; i++)
        #pragma unroll
        for (int j = 0; j < 4; j++) acc[i][j] = 0ull;

    int nch = Kt >> 4;
    #pragma unroll
    for (int p = 0; p < 2; p++) {
        int kc = p << 4;
        cpacg(sa  + (uint32_t)((((p*16 + ak) * 68) + am) << 2),
              Ab + (size_t)(kc + ak) * ldaT);
        cpacg(sbB + (uint32_t)((((p*16 + bk) * 128) + bn) << 2),
              Bb + (size_t)(kc + bk) * N);
        cpacg(sbB + (uint32_t)((((p*16 + bk + 8) * 128) + bn) << 2),
              Bb + (size_t)(kc + bk + 8) * N);
        asm volatile("cp.async.commit_group;");
    }

    int abase = wm * 32 + rg * 4;
    int bbase = wn * 32 + cg * 8;
    int s = 0;
    for (int ch = 0; ch < nch; ch++) {
        if (ch < nch - 1) asm volatile("cp.async.wait_group 1;");
        else              asm volatile("cp.async.wait_group 0;");
        __syncthreads();

        if (ch + 2 < nch) {
            int s2 = s + 2; if (s2 >= 3) s2 -= 3;
            int kc = (ch + 2) << 4;
            cpacg(sa  + (uint32_t)((((s2*16 + ak) * 68) + am) << 2),
                  Ab + (size_t)(kc + ak) * ldaT);
            cpacg(sbB + (uint32_t)((((s2*16 + bk) * 128) + bn) << 2),
                  Bb + (size_t)(kc + bk) * N);
            cpacg(sbB + (uint32_t)((((s2*16 + bk + 8) * 128) + bn) << 2),
                  Bb + (size_t)(kc + bk + 8) * N);
            asm volatile("cp.async.commit_group;");
        }

        const float* As_s = Asf + s * 1088;
        const float* Bs_s = Bsf + s * 2048;
        #pragma unroll
        for (int k = 0; k < 16; k++) {
            float4 av = *(const float4*)(As_s + k * 68 + abase);
            ulonglong2 q0 = *(const ulonglong2*)(Bs_s + k * 128 + bbase);
            ulonglong2 q1 = *(const ulonglong2*)(Bs_s + k * 128 + bbase + 4);
            u64 a0, a1, a2, a3;
            PACKDUP(a0, av.x); PACKDUP(a1, av.y); PACKDUP(a2, av.z); PACKDUP(a3, av.w);
            FMA2(acc[0][0], a0, q0.x); FMA2(acc[0][1], a0, q0.y);
            FMA2(acc[0][2], a0, q1.x); FMA2(acc[0][3], a0, q1.y);
            FMA2(acc[1][0], a1, q0.x); FMA2(acc[1][1], a1, q0.y);
            FMA2(acc[1][2], a1, q1.x); FMA2(acc[1][3], a1, q1.y);
            FMA2(acc[2][0], a2, q0.x); FMA2(acc[2][1], a2, q0.y);
            FMA2(acc[2][2], a2, q1.x); FMA2(acc[2][3], a2, q1.y);
            FMA2(acc[3][0], a3, q0.x); FMA2(acc[3][1], a3, q0.y);
            FMA2(acc[3][2], a3, q1.x); FMA2(acc[3][3], a3, q1.y);
        }
        s++; if (s >= 3) s = 0;
    }

    // epilogue: 4 rows x 8 contiguous cols
    int c0 = col0 + bbase;
    float vv[4][8];
    #pragma unroll
    for (int i = 0; i < 4; i++) {
        UNPACK2(vv[i][0], vv[i][1], acc[i][0]);
        UNPACK2(vv[i][2], vv[i][3], acc[i][1]);
        UNPACK2(vv[i][4], vv[i][5], acc[i][2]);
        UNPACK2(vv[i][6], vv[i][7], acc[i][3]);
    }
    #pragma unroll
    for (int j = 0; j < 8; j++) {
        float bj = bias ? __ldcg(bias + c0 + j) : 0.f;
        #pragma unroll
        for (int i = 0; i < 4; i++) {
            float v = vv[i][j] + bj;
            if (doRelu) v = fmaxf(v, 0.f);
            vv[i][j] = v;
        }
    }
    int r0 = row0 + abase;
    if (col0 < splitCol) {
        #pragma unroll
        for (int i = 0; i < 4; i++) {
            float4 o0 = {vv[i][0], vv[i][1], vv[i][2], vv[i][3]};
            float4 o1 = {vv[i][4], vv[i][5], vv[i][6], vv[i][7]};
            *(float4*)(Crow + (size_t)(r0 + i) * ldC + c0)     = o0;
            *(float4*)(Crow + (size_t)(r0 + i) * ldC + c0 + 4) = o1;
        }
    } else {
        #pragma unroll
        for (int j = 0; j < 8; j++) {
            float4 o = {vv[0][j], vv[1][j], vv[2][j], vv[3][j]};
            *(float4*)(CtrT + (size_t)(c0 + j - splitCol) * ldT + r0) = o;
        }
    }
}

// ---------------- the persistent mega-kernel -----------------------------------
#define IT 8
__global__ void __launch_bounds__(256, 2)
mega(const float* __restrict__ X, const int* __restrict__ adj,
     const float* __restrict__ pre_W1, const float* __restrict__ pre_b1,
     const float* __restrict__ pre_W2, const float* __restrict__ pre_b2,
     const float* __restrict__ msg_W1, const float* __restrict__ msg_b1,
     const float* __restrict__ msg_W2, const float* __restrict__ msg_b2,
     const float* __restrict__ gru_Wih, const float* __restrict__ gru_Whh,
     const float* __restrict__ gru_bih, const float* __restrict__ gru_bhh,
     const float* __restrict__ ro_W1, const float* __restrict__ ro_b1,
     const float* __restrict__ ro_W2, const float* __restrict__ ro_b2,
     float* __restrict__ out)
{
    __shared__ __align__(16) char smraw[37632];
    int bid = blockIdx.x, tid = threadIdx.x;

    // ---- P0: prep (XT, M2T, Wcat+bcat, bc) ----
    for (int i = bid * 256 + tid; i < 460800; i += G * 256) {
        if (i < 65536) {                           // XT[k][m] = X[m][k]
            int k = i >> 10, m = i & 1023;
            d_XT[i] = X[(size_t)m * Fn + k];
        } else if (i < 131072) {                   // M2T[k][m] = msg_W2[m][k]
            int j = i - 65536;
            int k = j >> 8, m = j & 255;
            d_M2T[j] = msg_W2[(size_t)m * Hn + k];
        } else if (i < 458752) {                   // Wcat[k][n] + bcat
            int j = i - 131072;
            int k = j / NC, n = j % NC;
            float v;
            if (n < 256)      v = msg_W1[(size_t)k * Hn + n];
            else if (n < 512) v = msg_W1[(size_t)(256 + k) * Hn + (n - 256)];
            else              v = gru_Whh[(size_t)k * 768 + (n - 512)];
            d_Wcat[j] = v;
            if (j < NC)
                d_bcat[j] = j < 256 ? msg_b1[j] : (j < 512 ? 0.f : gru_bhh[j - 512]);
        } else {                                   // bc[n]
            int n = i - 458752;
            float s = 0.f;
            for (int k = 0; k < Hn; k++)
                s += msg_b2[k] * gru_Wih[(size_t)k * 768 + n];
            d_bc[n] = s;
        }
    }
    gridbar();

    // ---- P1: Wc gemm (24 tiles) + pre-MLP1 (32 tiles) ----
    for (int t = bid; t < 56; t += G) {
        if (t < 24)
            gemm_tile(smraw, d_M2T, Hn, gru_Wih, 768, 256, 0,
                      nullptr, d_Wc, 768, 768, nullptr, 0, 0,
                      (t / 6) * 64, (t % 6) * 128);
        else {
            int t2 = t - 24;
            gemm_tile(smraw, d_XT, BN, pre_W1, 256, 64, 0,
                      pre_b1, nullptr, 0, 0, d_tT, BN, 1,
                      (t2 / 2) * 64, (t2 % 2) * 128);
        }
    }
    gridbar();

    // ---- P2: pre-MLP2 -> hT (32 tiles) ----
    for (int t = bid; t < 32; t += G)
        gemm_tile(smraw, d_tT, BN, pre_W2, 256, 256, 0,
                  pre_b2, nullptr, 0, 0, d_hT, BN, 0,
                  (t / 2) * 64, (t % 2) * 128);
    gridbar();

    for (int it = 0; it < Tn; it++) {
        // ---- P3: fused gemm, K-split 2 (320 tiles) ----
        for (int t = bid; t < 320; t += G) {
            int sp = t / 160, r = t % 160;
            gemm_tile(smraw, d_hT, BN, d_Wcat, NC, 128, sp * 128,
                      sp == 0 ? d_bcat : nullptr,
                      d_big2 + (size_t)sp * BN * 512, 512, 512,
                      d_ghT + (size_t)sp * 768 * BN, BN, 0,
                      (r / 10) * 64, (r % 10) * 128);
        }
        gridbar();

        // ---- P4: eagg (128 tiles of 8 rows) ----
        for (int t = bid; t < 128; t += G) {
            int b  = t >> 5;
            int i0 = (t & 31) * IT;
            int h  = tid;
            float (*adjf)[IT] = (float(*)[IT])smraw;
            const float* bA = d_big2;
            const float* bB = d_big2 + (size_t)BN * 512;

            __syncthreads();
            float hir[IT], acc[IT];
            #pragma unroll
            for (int q = 0; q < IT; q++) {
                adjf[h][q] = (float)adj[((size_t)(b * Nn + i0 + q)) * Nn + h];
                size_t o = ((size_t)(b * Nn + i0 + q)) * 512 + h;
                hir[q] = __ldcg(bA + o) + __ldcg(bB + o);
                acc[q] = 0.f;
            }
            __syncthreads();

            #pragma unroll 2
            for (int j = 0; j < Nn; j++) {
                size_t o = ((size_t)(b * Nn + j)) * 512 + 256 + h;
                float hjv = __ldcg(bA + o) + __ldcg(bB + o);
                float4 a04 = *(float4*)&adjf[j][0];
                float4 a47 = *(float4*)&adjf[j][4];
                acc[0] += a04.x * fmaxf(hir[0] + hjv, 0.f);
                acc[1] += a04.y * fmaxf(hir[1] + hjv, 0.f);
                acc[2] += a04.z * fmaxf(hir[2] + hjv, 0.f);
                acc[3] += a04.w * fmaxf(hir[3] + hjv, 0.f);
                acc[4] += a47.x * fmaxf(hir[4] + hjv, 0.f);
                acc[5] += a47.y * fmaxf(hir[5] + hjv, 0.f);
                acc[6] += a47.z * fmaxf(hir[6] + hjv, 0.f);
                acc[7] += a47.w * fmaxf(hir[7] + hjv, 0.f);
            }

            #pragma unroll
            for (int q = 0; q < IT; q++)
                d_aT[(size_t)h * BN + b * Nn + i0 + q] = acc[q];

            if (h < IT) {
                float s = 0.f;
                for (int j = 0; j < Nn; j++) s += adjf[j][h];
                d_deg[b * Nn + i0 + h] = s;
            }
        }
        gridbar();

        // ---- P5: gi gemm, K-split 4 (384 tiles) ----
        for (int t = bid; t < 384; t += G) {
            int sp = t / 96, r = t % 96;
            gemm_tile(smraw, d_aT, BN, d_Wc, 768, 64, sp * 64,
                      nullptr, nullptr, 0, 0,
                      d_giT + (size_t)sp * 768 * BN, BN, 0,
                      (r / 6) * 64, (r % 6) * 128);
        }
        gridbar();

        // ---- P6: GRU elementwise -> hT (sums 4 gi partials, 2 gh partials) ----
        for (int id = bid * 256 + tid; id < Hn * BN; id += G * 256) {
            int m = id & 1023, c = id >> 10;
            float dg = __ldcg(&d_deg[m]);
            float gv[3];
            #pragma unroll
            for (int gsl = 0; gsl < 3; gsl++) {
                size_t o = (size_t)(c + gsl * 256) * BN + m;
                float s = __ldcg(&d_giT[o]) + __ldcg(&d_giT[o + (size_t)768 * BN])
                        + __ldcg(&d_giT[o + (size_t)2 * 768 * BN])
                        + __ldcg(&d_giT[o + (size_t)3 * 768 * BN]);
                s += __ldcg(&gru_bih[c + gsl * 256]) + dg * __ldcg(&d_bc[c + gsl * 256]);
                s += __ldcg(&d_ghT[o]) + __ldcg(&d_ghT[o + (size_t)768 * BN]);
                gv[gsl] = s;
            }
            // gv = ir+hr, iz+hz, in + (gh n part); but n needs r * hn separately:
            // recompute: hn term must be scaled by r. Load gh n separately.
            size_t on = (size_t)(c + 512) * BN + m;
            float hn = __ldcg(&d_ghT[on]) + __ldcg(&d_ghT[on + (size_t)768 * BN]);
            float inn = gv[2] - hn;        // pure gi n + bias terms
            float r = 1.f / (1.f + __expf(-gv[0]));
            float z = 1.f / (1.f + __expf(-gv[1]));
            float n = tanhf(inn + r * hn);
            float hv = __ldcg(&d_hT[id]);
            d_hT[id] = (1.f - z) * n + z * hv;
        }
        gridbar();
    }

    // ---- P7: readout (blocks 0..3) ----
    if (bid < Bn) {
        float* gsh = (float*)smraw;
        float* hsh = (float*)(smraw + 1024);
        int b = bid, t = tid;

        float s = 0.f;
        const float* hrow = d_hT + (size_t)t * BN + b * Nn;
        #pragma unroll 4
        for (int i = 0; i < Nn; i++) s += __ldcg(hrow + i);
        gsh[t] = s;
        __syncthreads();

        float s2 = ro_b1[t];
        for (int k = 0; k < Hn; k++) s2 += gsh[k] * ro_W1[(size_t)k * Hn + t];
        hsh[t] = fmaxf(s2, 0.f);
        __syncthreads();

        if (t < An) {
            float s3 = ro_b2[t];
            for (int k = 0; k < Hn; k++) s3 += hsh[k] * ro_W2[(size_t)k * An + t];
            out[b * An + t] = s3;
        }
    }
}

// ---------------- host launch ---------------------------------------------------
extern "C" void kernel_launch(void* const* d_in, const int* in_sizes, int n_in,
                              void* d_out, int out_size)
{
    mega<<<G, 256>>>((const float*)d_in[0], (const int*)d_in[1],
                     (const float*)d_in[2], (const float*)d_in[3],
                     (const float*)d_in[4], (const float*)d_in[5],
                     (const float*)d_in[6], (const float*)d_in[7],
                     (const float*)d_in[8], (const float*)d_in[9],
                     (const float*)d_in[10], (const float*)d_in[11],
                     (const float*)d_in[12], (const float*)d_in[13],
                     (const float*)d_in[14], (const float*)d_in[15],
                     (const float*)d_in[16], (const float*)d_in[17],
                     (float*)d_out);
}

// round 14
// speedup vs baseline: 1.5985x; 1.5985x over previous
#include <cuda_runtime.h>
#include <cuda_bf16.h>
#include <math.h>
#include <stdint.h>

// Shapes: B=4, N=256, F=64, H=256, A=16, T=3
#define Bn 4
#define Nn 256
#define Fn 64
#define Hn 256
#define An 16
#define Tn 3
#define BN 1024
#define NC 1280
#define STAGES 3

typedef unsigned long long u64;

// ---------------- scratch (device globals) -----------------------------------
__device__ float d_XT  [Fn*BN];      // X^T        [64][1024]
__device__ float d_tT  [Hn*BN];      // pre-hidden^T
__device__ float d_hT  [Hn*BN];      // h^T
__device__ float d_aT  [Hn*BN];      // agg0^T
__device__ float d_M2T [Hn*Hn];      // msg_W2^T
__device__ float d_big2[BN*512];     // [hi+b1 | hj] row-major
__device__ float d_ghT [768*BN];     // gh^T (+bhh)
__device__ float d_giT [768*BN];     // gi^T
__device__ float d_deg [BN];
__device__ float d_Wc  [Hn*768];     // msg_W2 @ gru_Wih (row-major)
__device__ float d_bc  [768];        // msg_b2 @ gru_Wih
__device__ float d_Wcat[Hn*NC];      // [W1_i | W1_j | Whh] row-major
__device__ float d_bcat[NC];

// ---------------- helpers ------------------------------------------------------
#define FMA2(acc, a, b) \
    asm("fma.rn.f32x2 %0, %1, %2, %0;" : "+l"(acc) : "l"(a), "l"(b))
#define PACKDUP(d, s) \
    asm("mov.b64 %0, {%1, %1};" : "=l"(d) : "f"(s))
#define UNPACK2(lo, hi, s) \
    asm("mov.b64 {%0, %1}, %2;" : "=f"(lo), "=f"(hi) : "l"(s))

__device__ __forceinline__ void cpa16(void* s, const void* g) {
    uint32_t sa = (uint32_t)__cvta_generic_to_shared(s);
    asm volatile("cp.async.ca.shared.global [%0], [%1], 16;" :: "r"(sa), "l"(g));
}

// ---------------- pipelined fp32 GEMM, 64x128 tile ----------------------------
// C = f(A@B + bias + rowS*colV); A TRANSPOSED At[k][m] (ld ldaT); B row-major KxN.
// 128 thr; warps 2(m)x2(n), warp tile 32x64; thread 4 rows x 16 cols
// (cols interleaved: wn*64 + cg*4 + s*16, s=0..3 — conflict-free LDS).
// 3-stage cp.async pipeline, K-chunks of 16 (K mult of 16, K>=32).
// N multiple of 128. Block cols < splitCol -> Crow[r][c] (ld ldC);
// else CtrT[(c-splitCol)][r] (ld ldT).
__global__ void __launch_bounds__(128)
gemmW(const float* __restrict__ At, int ldaT,
      const float* __restrict__ Bm, int N, int K,
      const float* __restrict__ bias,
      const float* __restrict__ rowS, const float* __restrict__ colV,
      float* __restrict__ Crow, int ldC, int splitCol,
      float* __restrict__ CtrT, int ldT, int doRelu)
{
    __shared__ __align__(16) float As[STAGES][16][68];    // 13056 B
    __shared__ __align__(16) float Bs[STAGES][16][128];   // 24576 B

    int tid = threadIdx.x;
    int l = tid & 31, w = tid >> 5;
    int wm = w >> 1, wn = w & 1;
    int rg = l >> 2, cg = l & 3;
    int row0 = blockIdx.y * 64, col0 = blockIdx.x * 128;

    int lk = tid >> 4, lseg = (tid & 15) << 2;   // loader k-row (0..7), 16B seg
    const float* Abase = At + row0 + lseg;
    const float* Bbase0 = Bm + col0 + lseg;       // B first half (cols 0..63)
    const float* Bbase1 = Bm + col0 + 64 + lseg;  // second half

    u64 acc[4][8];    // 4 rows x 16 cols (8 pairs): [i][s*2 + p]
    #pragma unroll
    for (int i = 0; i < 4; i++)
        #pragma unroll
        for (int j = 0; j < 8; j++) acc[i][j] = 0ull;

    int nch = K >> 4;
    // prologue: chunks 0,1
    #pragma unroll
    for (int p = 0; p < 2; p++) {
        int kc = p << 4;
        cpa16(&As[p][lk ][lseg],      Abase  + (size_t)(kc + lk    ) * ldaT);
        cpa16(&As[p][lk + 8][lseg],   Abase  + (size_t)(kc + lk + 8) * ldaT);
        cpa16(&Bs[p][lk ][lseg],      Bbase0 + (size_t)(kc + lk    ) * N);
        cpa16(&Bs[p][lk + 8][lseg],   Bbase0 + (size_t)(kc + lk + 8) * N);
        cpa16(&Bs[p][lk ][64 + lseg], Bbase1 + (size_t)(kc + lk    ) * N);
        cpa16(&Bs[p][lk + 8][64 + lseg], Bbase1 + (size_t)(kc + lk + 8) * N);
        asm volatile("cp.async.commit_group;");
    }

    int mrow = wm * 32 + rg * 4;
    int ncb = wn * 64 + cg * 4;     // base col within tile; +s*16
    int s = 0;
    for (int ch = 0; ch < nch; ch++) {
        if (ch < nch - 1) asm volatile("cp.async.wait_group 1;");
        else              asm volatile("cp.async.wait_group 0;");
        __syncthreads();

        if (ch + 2 < nch) {
            int s2 = s + 2; if (s2 >= STAGES) s2 -= STAGES;
            int kc = (ch + 2) << 4;
            cpa16(&As[s2][lk ][lseg],      Abase  + (size_t)(kc + lk    ) * ldaT);
            cpa16(&As[s2][lk + 8][lseg],   Abase  + (size_t)(kc + lk + 8) * ldaT);
            cpa16(&Bs[s2][lk ][lseg],      Bbase0 + (size_t)(kc + lk    ) * N);
            cpa16(&Bs[s2][lk + 8][lseg],   Bbase0 + (size_t)(kc + lk + 8) * N);
            cpa16(&Bs[s2][lk ][64 + lseg], Bbase1 + (size_t)(kc + lk    ) * N);
            cpa16(&Bs[s2][lk + 8][64 + lseg], Bbase1 + (size_t)(kc + lk + 8) * N);
            asm volatile("cp.async.commit_group;");
        }

        #pragma unroll
        for (int k = 0; k < 16; k++) {
            float4 av = *(float4*)&As[s][k][mrow];
            ulonglong2 q0 = *(ulonglong2*)&Bs[s][k][ncb];
            ulonglong2 q1 = *(ulonglong2*)&Bs[s][k][ncb + 16];
            ulonglong2 q2 = *(ulonglong2*)&Bs[s][k][ncb + 32];
            ulonglong2 q3 = *(ulonglong2*)&Bs[s][k][ncb + 48];
            u64 a0, a1, a2, a3;
            PACKDUP(a0, av.x); PACKDUP(a1, av.y); PACKDUP(a2, av.z); PACKDUP(a3, av.w);
            FMA2(acc[0][0], a0, q0.x); FMA2(acc[0][1], a0, q0.y);
            FMA2(acc[0][2], a0, q1.x); FMA2(acc[0][3], a0, q1.y);
            FMA2(acc[0][4], a0, q2.x); FMA2(acc[0][5], a0, q2.y);
            FMA2(acc[0][6], a0, q3.x); FMA2(acc[0][7], a0, q3.y);
            FMA2(acc[1][0], a1, q0.x); FMA2(acc[1][1], a1, q0.y);
            FMA2(acc[1][2], a1, q1.x); FMA2(acc[1][3], a1, q1.y);
            FMA2(acc[1][4], a1, q2.x); FMA2(acc[1][5], a1, q2.y);
            FMA2(acc[1][6], a1, q3.x); FMA2(acc[1][7], a1, q3.y);
            FMA2(acc[2][0], a2, q0.x); FMA2(acc[2][1], a2, q0.y);
            FMA2(acc[2][2], a2, q1.x); FMA2(acc[2][3], a2, q1.y);
            FMA2(acc[2][4], a2, q2.x); FMA2(acc[2][5], a2, q2.y);
            FMA2(acc[2][6], a2, q3.x); FMA2(acc[2][7], a2, q3.y);
            FMA2(acc[3][0], a3, q0.x); FMA2(acc[3][1], a3, q0.y);
            FMA2(acc[3][2], a3, q1.x); FMA2(acc[3][3], a3, q1.y);
            FMA2(acc[3][4], a3, q2.x); FMA2(acc[3][5], a3, q2.y);
            FMA2(acc[3][6], a3, q3.x); FMA2(acc[3][7], a3, q3.y);
        }
        s++; if (s >= STAGES) s = 0;
    }

    // epilogue: 4 rows x 16 cols at col = col0 + ncb + s*16 + j (j=0..3 per pair grp)
    float vv[4][16];
    #pragma unroll
    for (int i = 0; i < 4; i++)
        #pragma unroll
        for (int sg = 0; sg < 4; sg++) {
            UNPACK2(vv[i][sg*4+0], vv[i][sg*4+1], acc[i][sg*2+0]);
            UNPACK2(vv[i][sg*4+2], vv[i][sg*4+3], acc[i][sg*2+1]);
        }

    int r0 = row0 + mrow;
    #pragma unroll
    for (int sg = 0; sg < 4; sg++) {
        int c = col0 + ncb + sg * 16;
        float bj[4], cvj[4];
        #pragma unroll
        for (int j = 0; j < 4; j++) {
            bj[j]  = bias ? bias[c + j] : 0.f;
            cvj[j] = rowS ? colV[c + j] : 0.f;
        }
        #pragma unroll
        for (int i = 0; i < 4; i++) {
            float rs = rowS ? rowS[r0 + i] : 0.f;
            #pragma unroll
            for (int j = 0; j < 4; j++) {
                float v = vv[i][sg*4+j] + bj[j] + rs * cvj[j];
                if (doRelu) v = fmaxf(v, 0.f);
                vv[i][sg*4+j] = v;
            }
        }
        if (c < splitCol) {
            #pragma unroll
            for (int i = 0; i < 4; i++) {
                float4 o = {vv[i][sg*4+0], vv[i][sg*4+1], vv[i][sg*4+2], vv[i][sg*4+3]};
                *(float4*)(Crow + (size_t)(r0 + i) * ldC + c) = o;
            }
        } else {
            #pragma unroll
            for (int j = 0; j < 4; j++) {
                float4 o = {vv[0][sg*4+j], vv[1][sg*4+j], vv[2][sg*4+j], vv[3][sg*4+j]};
                *(float4*)(CtrT + (size_t)(c + j - splitCol) * ldT + r0) = o;
            }
        }
    }
}

// ---------------- prep: transposes + Wcat/bcat -------------------------------
__global__ void prep(const float* __restrict__ X, const float* __restrict__ msgW2,
                     const float* __restrict__ msgW1, const float* __restrict__ Whh,
                     const float* __restrict__ msgb1, const float* __restrict__ bhh,
                     float* __restrict__ XT, float* __restrict__ M2T,
                     float* __restrict__ Wcat, float* __restrict__ bcat)
{
    int blk = blockIdx.x, t = threadIdx.x;
    if (blk < 256) {                     // XT[k][m] = X[m][k]
        int i = blk * 256 + t;
        int k = i >> 10, m = i & 1023;
        XT[i] = X[(size_t)m * Fn + k];
    } else if (blk < 512) {              // M2T[k][m] = msg_W2[m][k]
        int i = (blk - 256) * 256 + t;
        int k = i >> 8, m = i & 255;
        M2T[i] = msgW2[(size_t)m * Hn + k];
    } else {                             // Wcat[k][n]
        int i = (blk - 512) * 256 + t;
        int k = i / NC, n = i % NC;
        float v;
        if (n < 256)      v = msgW1[(size_t)k * Hn + n];
        else if (n < 512) v = msgW1[(size_t)(256 + k) * Hn + (n - 256)];
        else              v = Whh[(size_t)k * 768 + (n - 512)];
        Wcat[i] = v;
        if (i < NC)
            bcat[i] = i < 256 ? msgb1[i] : (i < 512 ? 0.f : bhh[i - 512]);
    }
}

// ---------------- E-aggregation ----------------------------------------------
#define IT 8
__global__ void eagg(const float* __restrict__ big2, const int* __restrict__ adj,
                     float* __restrict__ aT, float* __restrict__ deg)
{
    int b  = blockIdx.y;
    int i0 = blockIdx.x * IT;
    int h  = threadIdx.x;

    __shared__ float adjf[Nn][IT];

    float hir[IT], acc[IT];
    #pragma unroll
    for (int t = 0; t < IT; t++) {
        adjf[h][t] = (float)adj[((size_t)(b * Nn + i0 + t)) * Nn + h];
        hir[t] = big2[((size_t)(b * Nn + i0 + t)) * 512 + h];
        acc[t] = 0.f;
    }
    __syncthreads();

    const float* hjb = big2 + (size_t)b * Nn * 512 + 256;
    #pragma unroll 2
    for (int j = 0; j < Nn; j++) {
        float hjv = hjb[(size_t)j * 512 + h];
        float4 a04 = *(float4*)&adjf[j][0];
        float4 a47 = *(float4*)&adjf[j][4];
        acc[0] += a04.x * fmaxf(hir[0] + hjv, 0.f);
        acc[1] += a04.y * fmaxf(hir[1] + hjv, 0.f);
        acc[2] += a04.z * fmaxf(hir[2] + hjv, 0.f);
        acc[3] += a04.w * fmaxf(hir[3] + hjv, 0.f);
        acc[4] += a47.x * fmaxf(hir[4] + hjv, 0.f);
        acc[5] += a47.y * fmaxf(hir[5] + hjv, 0.f);
        acc[6] += a47.z * fmaxf(hir[6] + hjv, 0.f);
        acc[7] += a47.w * fmaxf(hir[7] + hjv, 0.f);
    }

    #pragma unroll
    for (int t = 0; t < IT; t++)
        aT[(size_t)h * BN + b * Nn + i0 + t] = acc[t];

    if (h < IT) {
        float s = 0.f;
        for (int j = 0; j < Nn; j++) s += adjf[j][h];
        deg[b * Nn + i0 + h] = s;
    }
}

// ---------------- bc = msg_b2 @ gru_Wih (one warp per output) ----------------
__global__ void bck(const float* __restrict__ b2, const float* __restrict__ Wih,
                    float* __restrict__ bc)
{
    int warp = (blockIdx.x * blockDim.x + threadIdx.x) >> 5;
    int lane = threadIdx.x & 31;
    float s = 0.f;
    for (int k = lane; k < Hn; k += 32)
        s += b2[k] * Wih[(size_t)k * 768 + warp];
    #pragma unroll
    for (int o = 16; o; o >>= 1) s += __shfl_xor_sync(0xffffffffu, s, o);
    if (lane == 0) bc[warp] = s;
}

// ---------------- GRU elementwise (coalesced on transposed layouts) ----------
__global__ void gru(const float* __restrict__ giT, const float* __restrict__ ghT,
                    float* __restrict__ hT)
{
    int id = blockIdx.x * 256 + threadIdx.x;   // over Hn*BN, m fastest
    int m = id & 1023, c = id >> 10;
    float ir = giT[(size_t)c * BN + m];
    float iz = giT[(size_t)(c + 256) * BN + m];
    float in = giT[(size_t)(c + 512) * BN + m];
    float hr = ghT[(size_t)c * BN + m];
    float hz = ghT[(size_t)(c + 256) * BN + m];
    float hn = ghT[(size_t)(c + 512) * BN + m];
    float r = 1.f / (1.f + __expf(-(ir + hr)));
    float z = 1.f / (1.f + __expf(-(iz + hz)));
    float n = tanhf(in + r * hn);
    hT[id] = (1.f - z) * n + z * hT[id];
}

// ---------------- readout ------------------------------------------------------
__global__ void readout(const float* __restrict__ hT,
                        const float* __restrict__ W1, const float* __restrict__ b1,
                        const float* __restrict__ W2, const float* __restrict__ b2,
                        float* __restrict__ out)
{
    __shared__ float gsh[Hn];
    __shared__ float hsh[Hn];
    int b = blockIdx.x, t = threadIdx.x;

    float s = 0.f;
    const float* hrow = hT + (size_t)t * BN + b * Nn;
    #pragma unroll 4
    for (int i = 0; i < Nn; i++) s += hrow[i];
    gsh[t] = s;
    __syncthreads();

    float s2 = b1[t];
    for (int k = 0; k < Hn; k++) s2 += gsh[k] * W1[(size_t)k * Hn + t];
    hsh[t] = fmaxf(s2, 0.f);
    __syncthreads();

    if (t < An) {
        float s3 = b2[t];
        for (int k = 0; k < Hn; k++) s3 += hsh[k] * W2[(size_t)k * An + t];
        out[b * An + t] = s3;
    }
}

// ---------------- host launch ---------------------------------------------------
extern "C" void kernel_launch(void* const* d_in, const int* in_sizes, int n_in,
                              void* d_out, int out_size)
{
    const float* X       = (const float*)d_in[0];
    const int*   adj     = (const int*)  d_in[1];
    const float* pre_W1  = (const float*)d_in[2];
    const float* pre_b1  = (const float*)d_in[3];
    const float* pre_W2  = (const float*)d_in[4];
    const float* pre_b2  = (const float*)d_in[5];
    const float* msg_W1  = (const float*)d_in[6];
    const float* msg_b1  = (const float*)d_in[7];
    const float* msg_W2  = (const float*)d_in[8];
    const float* msg_b2  = (const float*)d_in[9];
    const float* gru_Wih = (const float*)d_in[10];
    const float* gru_Whh = (const float*)d_in[11];
    const float* gru_bih = (const float*)d_in[12];
    const float* gru_bhh = (const float*)d_in[13];
    const float* ro_W1   = (const float*)d_in[14];
    const float* ro_b1   = (const float*)d_in[15];
    const float* ro_W2   = (const float*)d_in[16];
    const float* ro_b2   = (const float*)d_in[17];

    float *XT,*tT,*hT,*aT,*M2T,*big2,*ghT,*giT,*deg,*Wc,*bc,*Wcat,*bcat;
    cudaGetSymbolAddress((void**)&XT,  d_XT);
    cudaGetSymbolAddress((void**)&tT,  d_tT);
    cudaGetSymbolAddress((void**)&hT,  d_hT);
    cudaGetSymbolAddress((void**)&aT,  d_aT);
    cudaGetSymbolAddress((void**)&M2T, d_M2T);
    cudaGetSymbolAddress((void**)&big2,d_big2);
    cudaGetSymbolAddress((void**)&ghT, d_ghT);
    cudaGetSymbolAddress((void**)&giT, d_giT);
    cudaGetSymbolAddress((void**)&deg, d_deg);
    cudaGetSymbolAddress((void**)&Wc,  d_Wc);
    cudaGetSymbolAddress((void**)&bc,  d_bc);
    cudaGetSymbolAddress((void**)&Wcat,d_Wcat);
    cudaGetSymbolAddress((void**)&bcat,d_bcat);

    // prep: XT, M2T, Wcat, bcat; bc
    prep<<<512 + Hn * NC / 256, 256>>>(X, msg_W2, msg_W1, gru_Whh, msg_b1, gru_bhh,
                                       XT, M2T, Wcat, bcat);
    bck<<<96, 256>>>(msg_b2, gru_Wih, bc);

    // Wc = msg_W2 @ gru_Wih (row-major out): M=256, N=768, K=256
    gemmW<<<dim3(768/128, 256/64), 128>>>(M2T, Hn, gru_Wih, 768, Hn,
                                          nullptr, nullptr, nullptr,
                                          Wc, 768, 768, nullptr, 0, 0);

    // pre-MLP: tT = relu(X@W1+b1)^T ; hT = (t@W2+b2)^T   (M=1024, N=256)
    gemmW<<<dim3(256/128, BN/64), 128>>>(XT, BN, pre_W1, Hn, Fn,
                                         pre_b1, nullptr, nullptr,
                                         nullptr, 0, 0, tT, BN, 1);
    gemmW<<<dim3(256/128, BN/64), 128>>>(tT, BN, pre_W2, Hn, Hn,
                                         pre_b2, nullptr, nullptr,
                                         nullptr, 0, 0, hT, BN, 0);

    for (int it = 0; it < Tn; it++) {
        // [hi+b1 | hj] -> big2 (row-major), gh+bhh -> ghT (transposed). N=1280.
        gemmW<<<dim3(NC/128, BN/64), 128>>>(hT, BN, Wcat, NC, Hn,
                                            bcat, nullptr, nullptr,
                                            big2, 512, 512, ghT, BN, 0);
        eagg<<<dim3(Nn / IT, Bn), 256>>>(big2, adj, aT, deg);
        // giT = (agg0 @ Wc + deg*bc + bih)^T.  N=768.
        gemmW<<<dim3(768/128, BN/64), 128>>>(aT, BN, Wc, 768, Hn,
                                             gru_bih, deg, bc,
                                             nullptr, 0, 0, giT, BN, 0);
        gru<<<Hn * BN / 256, 256>>>(giT, ghT, hT);
    }

    readout<<<Bn, 256>>>(hT, ro_W1, ro_b1, ro_W2, ro_b2, (float*)d_out);
}